// round 2
// baseline (speedup 1.0000x reference)
#include <cuda_runtime.h>
#include <cuda_bf16.h>
#include <cstdint>
#include <cstddef>

// ============================================================================
// Quantized FFN via exact integer GEMMs:
//   out = quant_linear(relu(quant_linear(x, w1, b1)), w2, b2)
// Activations -> uint8 codes, weights -> int8 codes, mma.sync u8*s8 -> s32,
// epilogue applies per-column float scale + pre-rounded bias.
// (tcgen05 is unavailable: harness PTX targets compute_103, not sm_103a.)
// ============================================================================

#define EPSQ 1e-8f

static constexpr int M_TOT = 8192;   // B*S
static constexpr int D_DIM = 1024;
static constexpr int F_DIM = 4096;

// ---------------- scratch (static device globals; no allocation) ------------
__device__ float g_maxx;
__device__ float g_maxh;
__device__ uint8_t g_qx[(size_t)M_TOT * D_DIM];        // 8 MB
__device__ int8_t  g_qw1[(size_t)F_DIM * D_DIM];       // 4 MB
__device__ float   g_sw1[F_DIM];
__device__ float   g_scale1[F_DIM];
__device__ float   g_badd1[F_DIM];
__device__ int8_t  g_qw2[(size_t)D_DIM * F_DIM];       // 4 MB
__device__ float   g_sw2[D_DIM];
__device__ float   g_h[(size_t)M_TOT * F_DIM];         // 128 MB
__device__ uint8_t g_qh[(size_t)M_TOT * F_DIM];        // 32 MB

// ---------------- PTX helpers ------------------------------------------------
__device__ __forceinline__ uint32_t smem_u32(const void* p) {
    uint32_t a;
    asm("{ .reg .u64 t; cvta.to.shared.u64 t, %1; cvt.u32.u64 %0, t; }"
        : "=r"(a) : "l"(p));
    return a;
}

__device__ __forceinline__ void cp16(uint32_t dst, const void* src) {
    asm volatile("cp.async.cg.shared.global [%0], [%1], 16;" :: "r"(dst), "l"(src));
}
#define CP_COMMIT() asm volatile("cp.async.commit_group;" ::: "memory")
#define CP_WAIT1()  asm volatile("cp.async.wait_group 1;" ::: "memory")

__device__ __forceinline__ uint32_t lds32(uint32_t a) {
    uint32_t v;
    asm volatile("ld.shared.b32 %0, [%1];" : "=r"(v) : "r"(a));
    return v;
}

// u8 (A, row-major) x s8 (B, k-contiguous per n) -> s32, m16n8k32
__device__ __forceinline__ void mma_u8s8(int* c, const uint32_t* a, const uint32_t* b) {
    asm volatile(
        "mma.sync.aligned.m16n8k32.row.col.s32.u8.s8.s32 "
        "{%0,%1,%2,%3}, {%4,%5,%6,%7}, {%8,%9}, {%0,%1,%2,%3};"
        : "+r"(c[0]), "+r"(c[1]), "+r"(c[2]), "+r"(c[3])
        : "r"(a[0]), "r"(a[1]), "r"(a[2]), "r"(a[3]), "r"(b[0]), "r"(b[1]));
}

// ---------------- elementwise / reduction kernels ----------------------------
__global__ void init_kernel() {
    g_maxx = 0.0f;
    g_maxh = 0.0f;
}

__global__ void max_x_kernel(const float* __restrict__ x) {
    float m = 0.0f;
    const int n4 = (M_TOT * D_DIM) / 4;
    for (int i = blockIdx.x * blockDim.x + threadIdx.x; i < n4; i += gridDim.x * blockDim.x) {
        float4 v = reinterpret_cast<const float4*>(x)[i];
        m = fmaxf(m, fmaxf(fmaxf(v.x, v.y), fmaxf(v.z, v.w)));
    }
    #pragma unroll
    for (int o = 16; o; o >>= 1) m = fmaxf(m, __shfl_xor_sync(0xffffffffu, m, o));
    __shared__ float red[8];
    int wid = threadIdx.x >> 5, lid = threadIdx.x & 31;
    if (lid == 0) red[wid] = m;
    __syncthreads();
    if (threadIdx.x == 0) {
        float b = red[0];
        int nw = blockDim.x >> 5;
        for (int i = 1; i < nw; i++) b = fmaxf(b, red[i]);
        atomicMax(reinterpret_cast<unsigned int*>(&g_maxx), __float_as_uint(fmaxf(b, 0.0f)));
    }
}

// per-row |max| scale for a [R, K] weight; optionally also scale1/badd1 (w1)
template <int K, bool W1>
__global__ void scales_w_kernel(const float* __restrict__ w, const float* __restrict__ b1) {
    const int r = blockIdx.x;
    const float* row = w + (size_t)r * K;
    const int t = threadIdx.x;  // 128
    float m = 0.0f;
    for (int i = t; i < K; i += 128) m = fmaxf(m, fabsf(row[i]));
    #pragma unroll
    for (int o = 16; o; o >>= 1) m = fmaxf(m, __shfl_xor_sync(0xffffffffu, m, o));
    __shared__ float red[4];
    if ((t & 31) == 0) red[t >> 5] = m;
    __syncthreads();
    if (t == 0) {
        float mx = fmaxf(fmaxf(red[0], red[1]), fmaxf(red[2], red[3]));
        float s = __fdiv_rn(fmaxf(mx, EPSQ), 127.0f);
        if (W1) {
            g_sw1[r] = s;
            float s1 = __fdiv_rn(fmaxf(g_maxx, EPSQ), 255.0f);
            float sc = s1 * s;
            g_scale1[r] = sc;
            g_badd1[r] = rintf(__fdiv_rn(b1[r], sc)) * sc;
        } else {
            g_sw2[r] = s;
        }
    }
}

// elementwise weight quantization, coalesced; row = idx4*4 / K
template <int K>
__global__ void quant_w_kernel(const float* __restrict__ w, const float* __restrict__ sw,
                               int8_t* __restrict__ qw, int n_elems) {
    const int n4 = n_elems / 4;
    for (int i = blockIdx.x * blockDim.x + threadIdx.x; i < n4; i += gridDim.x * blockDim.x) {
        float4 v = reinterpret_cast<const float4*>(w)[i];
        float s = sw[(i * 4) / K];
        float q0 = fminf(fmaxf(rintf(__fdiv_rn(v.x, s)), -128.0f), 127.0f);
        float q1 = fminf(fmaxf(rintf(__fdiv_rn(v.y, s)), -128.0f), 127.0f);
        float q2 = fminf(fmaxf(rintf(__fdiv_rn(v.z, s)), -128.0f), 127.0f);
        float q3 = fminf(fmaxf(rintf(__fdiv_rn(v.w, s)), -128.0f), 127.0f);
        char4 o;
        o.x = (char)(int)q0; o.y = (char)(int)q1; o.z = (char)(int)q2; o.w = (char)(int)q3;
        reinterpret_cast<char4*>(qw)[i] = o;
    }
}

__global__ void quant_x_kernel(const float* __restrict__ x) {
    const float s1 = __fdiv_rn(fmaxf(g_maxx, EPSQ), 255.0f);
    const int n4 = (M_TOT * D_DIM) / 4;
    for (int i = blockIdx.x * blockDim.x + threadIdx.x; i < n4; i += gridDim.x * blockDim.x) {
        float4 v = reinterpret_cast<const float4*>(x)[i];
        float q0 = fminf(fmaxf(rintf(__fdiv_rn(v.x, s1)), 0.0f), 255.0f);
        float q1 = fminf(fmaxf(rintf(__fdiv_rn(v.y, s1)), 0.0f), 255.0f);
        float q2 = fminf(fmaxf(rintf(__fdiv_rn(v.z, s1)), 0.0f), 255.0f);
        float q3 = fminf(fmaxf(rintf(__fdiv_rn(v.w, s1)), 0.0f), 255.0f);
        uchar4 o;
        o.x = (unsigned char)(int)q0; o.y = (unsigned char)(int)q1;
        o.z = (unsigned char)(int)q2; o.w = (unsigned char)(int)q3;
        reinterpret_cast<uchar4*>(g_qx)[i] = o;
    }
}

__global__ void quant_h_kernel() {
    const float s2 = __fdiv_rn(fmaxf(g_maxh, EPSQ), 255.0f);
    const size_t n4 = ((size_t)M_TOT * F_DIM) / 4;
    for (size_t i = blockIdx.x * (size_t)blockDim.x + threadIdx.x; i < n4;
         i += (size_t)gridDim.x * blockDim.x) {
        float4 v = reinterpret_cast<const float4*>(g_h)[i];
        float q0 = fminf(fmaxf(rintf(__fdiv_rn(v.x, s2)), 0.0f), 255.0f);
        float q1 = fminf(fmaxf(rintf(__fdiv_rn(v.y, s2)), 0.0f), 255.0f);
        float q2 = fminf(fmaxf(rintf(__fdiv_rn(v.z, s2)), 0.0f), 255.0f);
        float q3 = fminf(fmaxf(rintf(__fdiv_rn(v.w, s2)), 0.0f), 255.0f);
        uchar4 o;
        o.x = (unsigned char)(int)q0; o.y = (unsigned char)(int)q1;
        o.z = (unsigned char)(int)q2; o.w = (unsigned char)(int)q3;
        reinterpret_cast<uchar4*>(g_qh)[i] = o;
    }
}

// ---------------- int8 GEMM (mma.sync u8 x s8 -> s32) ------------------------
// D[m,n] = sum_k A[m,k]*B[n,k]; CTA tile 128x128x64; 8 warps as 2(M)x4(N);
// warp tile 64x32; mma m16n8k32; cp.async double buffering.
static constexpr int TM = 128, TN = 128, TK = 64;
static constexpr int AST = 80;                // smem row stride (64 + 16 pad)
static constexpr int TILEB = 128 * AST;       // 10240 bytes per operand tile

template <int KTOT, int NTOT, bool G1>
__global__ void __launch_bounds__(256, 2) gemm_imma(float* __restrict__ outp,
                                                    const float* __restrict__ bias)
{
    __shared__ __align__(16) unsigned char sA[2][TILEB];
    __shared__ __align__(16) unsigned char sB[2][TILEB];
    __shared__ float csc[TN], cbd[TN];
    __shared__ float wred[8];

    const int tid = threadIdx.x, lane = tid & 31, wid = tid >> 5;
    const int warp_m = wid & 1, warp_n = wid >> 1;
    const int m0 = blockIdx.y * TM, n0 = blockIdx.x * TN;

    const uint8_t* __restrict__ A = G1 ? g_qx : g_qh;
    const int8_t*  __restrict__ B = G1 ? g_qw1 : g_qw2;

    if (tid < TN) {
        int n = n0 + tid;
        if (G1) {
            csc[tid] = g_scale1[n];
            cbd[tid] = g_badd1[n];
        } else {
            float s2 = __fdiv_rn(fmaxf(g_maxh, EPSQ), 255.0f);
            float sc = s2 * g_sw2[n];
            csc[tid] = sc;
            cbd[tid] = rintf(__fdiv_rn(bias[n], sc)) * sc;
        }
    }

    const uint32_t aAddr = smem_u32(sA);
    const uint32_t bAddr = smem_u32(sB);

    const int NT = KTOT / TK;
    const int lr = tid >> 2, lkv = tid & 3;  // load row / 16B-chunk (it=0 half)

    auto load_tile = [&](int t, int bufsel) {
        const size_t kb = (size_t)t * TK;
        #pragma unroll
        for (int it = 0; it < 2; ++it) {
            int r = lr + it * 64;
            uint32_t soff = (uint32_t)(bufsel * TILEB + r * AST + lkv * 16);
            cp16(aAddr + soff, A + (size_t)(m0 + r) * KTOT + kb + lkv * 16);
            cp16(bAddr + soff, B + (size_t)(n0 + r) * KTOT + kb + lkv * 16);
        }
    };

    load_tile(0, 0); CP_COMMIT();
    load_tile(1, 1); CP_COMMIT();

    int acc[4][4][4];
    #pragma unroll
    for (int i = 0; i < 4; ++i)
        #pragma unroll
        for (int j = 0; j < 4; ++j)
            #pragma unroll
            for (int k = 0; k < 4; ++k) acc[i][j][k] = 0;

    const int arow = (lane >> 2), acol = (lane & 3) * 4;

    for (int t = 0; t < NT; ++t) {
        CP_WAIT1();
        __syncthreads();
        const int buf = t & 1;
        const uint32_t aB = aAddr + buf * TILEB;
        const uint32_t bB = bAddr + buf * TILEB;
        #pragma unroll
        for (int ks = 0; ks < 2; ++ks) {
            uint32_t af[4][4], bf[4][2];
            #pragma unroll
            for (int fm = 0; fm < 4; ++fm) {
                uint32_t base = aB + (uint32_t)((warp_m * 64 + fm * 16 + arow) * AST
                                                + ks * 32 + acol);
                af[fm][0] = lds32(base);
                af[fm][1] = lds32(base + 8 * AST);
                af[fm][2] = lds32(base + 16);
                af[fm][3] = lds32(base + 8 * AST + 16);
            }
            #pragma unroll
            for (int fn = 0; fn < 4; ++fn) {
                uint32_t base = bB + (uint32_t)((warp_n * 32 + fn * 8 + arow) * AST
                                                + ks * 32 + acol);
                bf[fn][0] = lds32(base);
                bf[fn][1] = lds32(base + 16);
            }
            #pragma unroll
            for (int fm = 0; fm < 4; ++fm)
                #pragma unroll
                for (int fn = 0; fn < 4; ++fn)
                    mma_u8s8(acc[fm][fn], af[fm], bf[fn]);
        }
        __syncthreads();
        if (t + 2 < NT) load_tile(t + 2, buf);
        CP_COMMIT();
    }

    // -------- epilogue: float scale + bias (+ReLU+max for G1) ---------------
    float* __restrict__ O = G1 ? g_h : outp;
    float lmax = 0.0f;
    #pragma unroll
    for (int fm = 0; fm < 4; ++fm) {
        const int r0 = m0 + warp_m * 64 + fm * 16 + (lane >> 2);
        #pragma unroll
        for (int fn = 0; fn < 4; ++fn) {
            const int cl = warp_n * 32 + fn * 8 + (lane & 3) * 2;
            const float s0 = csc[cl], s1 = csc[cl + 1];
            const float d0 = cbd[cl], d1 = cbd[cl + 1];
            float v00 = s0 * (float)acc[fm][fn][0] + d0;
            float v01 = s1 * (float)acc[fm][fn][1] + d1;
            float v10 = s0 * (float)acc[fm][fn][2] + d0;
            float v11 = s1 * (float)acc[fm][fn][3] + d1;
            if (G1) {
                v00 = fmaxf(v00, 0.0f); v01 = fmaxf(v01, 0.0f);
                v10 = fmaxf(v10, 0.0f); v11 = fmaxf(v11, 0.0f);
                lmax = fmaxf(lmax, fmaxf(fmaxf(v00, v01), fmaxf(v10, v11)));
            }
            float2 p0 = make_float2(v00, v01);
            float2 p1 = make_float2(v10, v11);
            *reinterpret_cast<float2*>(O + (size_t)r0 * NTOT + n0 + cl) = p0;
            *reinterpret_cast<float2*>(O + (size_t)(r0 + 8) * NTOT + n0 + cl) = p1;
        }
    }

    if (G1) {
        #pragma unroll
        for (int o = 16; o; o >>= 1) lmax = fmaxf(lmax, __shfl_xor_sync(0xffffffffu, lmax, o));
        if (lane == 0) wred[wid] = lmax;
        __syncthreads();
        if (tid == 0) {
            float b = wred[0];
            #pragma unroll
            for (int i = 1; i < 8; i++) b = fmaxf(b, wred[i]);
            atomicMax(reinterpret_cast<unsigned int*>(&g_maxh), __float_as_uint(b));
        }
    }
}

// ---------------- launcher ---------------------------------------------------
extern "C" void kernel_launch(void* const* d_in, const int* in_sizes, int n_in,
                              void* d_out, int out_size)
{
    const float* x  = (const float*)d_in[0];
    const float* w1 = (const float*)d_in[1];
    const float* b1 = (const float*)d_in[2];
    const float* w2 = (const float*)d_in[3];
    const float* b2 = (const float*)d_in[4];
    float* out = (float*)d_out;

    int8_t* qw1p; cudaGetSymbolAddress((void**)&qw1p, g_qw1);
    int8_t* qw2p; cudaGetSymbolAddress((void**)&qw2p, g_qw2);
    float* sw1p;  cudaGetSymbolAddress((void**)&sw1p, g_sw1);
    float* sw2p;  cudaGetSymbolAddress((void**)&sw2p, g_sw2);

    init_kernel<<<1, 1>>>();
    max_x_kernel<<<256, 256>>>(x);
    scales_w_kernel<D_DIM, true><<<F_DIM, 128>>>(w1, b1);
    scales_w_kernel<F_DIM, false><<<D_DIM, 128>>>(w2, nullptr);
    quant_w_kernel<D_DIM><<<512, 256>>>(w1, sw1p, qw1p, F_DIM * D_DIM);
    quant_w_kernel<F_DIM><<<512, 256>>>(w2, sw2p, qw2p, D_DIM * F_DIM);
    quant_x_kernel<<<1024, 256>>>(x);
    gemm_imma<D_DIM, F_DIM, true>
        <<<dim3(F_DIM / TN, M_TOT / TM), 256>>>(nullptr, nullptr);
    quant_h_kernel<<<2048, 256>>>();
    gemm_imma<F_DIM, D_DIM, false>
        <<<dim3(D_DIM / TN, M_TOT / TM), 256>>>(out, b2);
}